// round 4
// baseline (speedup 1.0000x reference)
#include <cuda_runtime.h>
#include <math.h>

#define BLOCK 1024
#define NWARP 32

__device__ __forceinline__ float wredsum(float x) {
#pragma unroll
    for (int o = 16; o > 0; o >>= 1) x += __shfl_down_sync(0xffffffffu, x, o);
    return x;
}
__device__ __forceinline__ float wredmax(float x) {
#pragma unroll
    for (int o = 16; o > 0; o >>= 1) x = fmaxf(x, __shfl_down_sync(0xffffffffu, x, o));
    return x;
}

__global__ void __launch_bounds__(BLOCK, 1)
spectral_rank2_kernel(const float4* __restrict__ in4, float4* __restrict__ out4) {
    __shared__ float sb[4][NWARP];
    __shared__ float r1[4];   // Sc, Ss, qmax, max(-q)
    __shared__ float r2[3];   // Gram a, b, g
    const int t = threadIdx.x;
    const int lane = t & 31, w = t >> 5;

    // ---- Phase 1: load + feature transform.
    // sigmoid(|x|) = 1/(1+e), v ~= e, e = exp(-|x|).
    // Normalized feature direction: (1, q)/sqrt(1+q^2), q = e + e^2.
    float4 x4 = in4[t];
    float xs[4] = {x4.x, x4.y, x4.z, x4.w};
    float q[4], cw[4];
    float pc = 0.f, ps = 0.f, pqmx = -3.0e38f, pqmn = -3.0e38f;
#pragma unroll
    for (int k = 0; k < 4; k++) {
        float e  = __expf(-fabsf(xs[k]));
        float qq = fmaf(e, e, e);                  // q = e + e^2
        float c  = rsqrtf(fmaf(qq, qq, 1.f));
        q[k] = qq; cw[k] = c;
        pc += c; ps += qq * c;
        pqmx = fmaxf(pqmx, qq);
        pqmn = fmaxf(pqmn, -qq);
    }
    // ---- R1: Sc, Ss sums + q extremes (4 parallel chains, one barrier pair).
    {
        float a = wredsum(pc), b = wredsum(ps);
        float m = wredmax(pqmx), n = wredmax(pqmn);
        if (lane == 0) { sb[0][w] = a; sb[1][w] = b; sb[2][w] = m; sb[3][w] = n; }
        __syncthreads();
        if (w == 0) {
            float a2 = wredsum(sb[0][lane]);
            float b2 = wredsum(sb[1][lane]);
            float m2 = wredmax(sb[2][lane]);
            float n2 = wredmax(sb[3][lane]);
            if (lane == 0) { r1[0] = a2; r1[1] = b2; r1[2] = m2; r1[3] = n2; }
        }
        __syncthreads();
    }
    const float Sc = r1[0], Ss = r1[1], qmx = r1[2], qmn = -r1[3];

    // ---- Phase 2: dis = rsqrt(degree); cdis = c*dis; Gram partials.
    // u = cdis, v = q*cdis; a=sum u^2, b=sum uv, g=sum v^2.
    float cd[4];
    float pa = 0.f, pb = 0.f, pg = 0.f;
#pragma unroll
    for (int k = 0; k < 4; k++) {
        float d    = fmaf(q[k], Ss, Sc) * cw[k];   // degree
        float dis  = rsqrtf(d);
        float cdis = cw[k] * dis;
        cd[k] = cdis;
        float t2  = cdis * cdis;
        float t2q = t2 * q[k];
        pa += t2;
        pb += t2q;
        pg = fmaf(t2q, q[k], pg);
    }
    // ---- R2: Gram sums.
    {
        float a = wredsum(pa), b = wredsum(pb), g = wredsum(pg);
        if (lane == 0) { sb[0][w] = a; sb[1][w] = b; sb[2][w] = g; }
        __syncthreads();
        if (w == 0) {
            float a2 = wredsum(sb[0][lane]);
            float b2 = wredsum(sb[1][lane]);
            float g2 = wredsum(sb[2][lane]);
            if (lane == 0) { r2[0] = a2; r2[1] = b2; r2[2] = g2; }
        }
        __syncthreads();
    }
    const float A = r2[0], B = r2[1], G = r2[2];

    // ---- Phase 3 (per-thread, no barrier): 2x2 eigensolve, second eigenvalue.
    float diff = 0.5f * (A - G);
    float rr = sqrtf(fmaf(diff, diff, B * B));
    float al, be;
    if (diff >= 0.f) { al = B;         be = -(diff + rr); }
    else             { al = rr - diff; be = -B;            }

    // F is monotone in q (see analysis) -> extremes at q_min / q_max.
    // Evaluate endpoints with the EXACT same op sequence as the per-element
    // path so min/max are bit-consistent.
    float Fe[2];
    float qe[2] = {qmn, qmx};
#pragma unroll
    for (int k = 0; k < 2; k++) {
        float c    = rsqrtf(fmaf(qe[k], qe[k], 1.f));
        float d    = fmaf(qe[k], Ss, Sc) * c;
        float cdis = c * rsqrtf(d);
        Fe[k] = fmaf(be, qe[k], al) * cdis;
    }
    float Fmn = fminf(Fe[0], Fe[1]);
    float Fmx = fmaxf(Fe[0], Fe[1]);
    float pivot = (fabsf(Fmx) >= fabsf(Fmn)) ? Fmx : Fmn;
    float sgn = (pivot >= 0.f) ? 1.f : -1.f;
    float mn = (sgn > 0.f) ? Fmn : -Fmx;
    float mx = (sgn > 0.f) ? Fmx : -Fmn;
    float scale = __fdividef(1.f, mx - mn + 1e-10f);
    float a1 = sgn * scale, a0 = -mn * scale;   // out = F*a1 + a0

    // ---- Phase 4: Fiedler values + fused normalize + store.
    float4 o;
    float F0 = fmaf(be, q[0], al) * cd[0];
    float F1 = fmaf(be, q[1], al) * cd[1];
    float F2 = fmaf(be, q[2], al) * cd[2];
    float F3 = fmaf(be, q[3], al) * cd[3];
    o.x = fmaf(F0, a1, a0);
    o.y = fmaf(F1, a1, a0);
    o.z = fmaf(F2, a1, a0);
    o.w = fmaf(F3, a1, a0);
    out4[t] = o;
}

extern "C" void kernel_launch(void* const* d_in, const int* in_sizes, int n_in,
                              void* d_out, int out_size) {
    (void)in_sizes; (void)n_in; (void)out_size;
    const float4* in = (const float4*)d_in[0];
    float4* out = (float4*)d_out;
    spectral_rank2_kernel<<<1, BLOCK>>>(in, out);
}

// round 6
// speedup vs baseline: 1.0966x; 1.0966x over previous
#include <cuda_runtime.h>
#include <math.h>

#define BLOCK 1024
#define NWARP 32

// Warp sum, result only needed in lane 0 (shfl_down chain).
__device__ __forceinline__ float wsum_down(float x) {
#pragma unroll
    for (int o = 16; o > 0; o >>= 1) x += __shfl_down_sync(0xffffffffu, x, o);
    return x;
}
// Warp sum, result in ALL lanes (butterfly).
__device__ __forceinline__ float wsum_bfly(float x) {
#pragma unroll
    for (int o = 16; o > 0; o >>= 1) x += __shfl_xor_sync(0xffffffffu, x, o);
    return x;
}
// Integer REDUX (sm_103-supported). Positive-float bit patterns are
// order-isomorphic to u32, so these give float min/max for q > 0.
__device__ __forceinline__ unsigned redux_max_u32(unsigned v) {
    unsigned r;
    asm volatile("redux.sync.max.u32 %0, %1, 0xffffffff;" : "=r"(r) : "r"(v));
    return r;
}
__device__ __forceinline__ unsigned redux_min_u32(unsigned v) {
    unsigned r;
    asm volatile("redux.sync.min.u32 %0, %1, 0xffffffff;" : "=r"(r) : "r"(v));
    return r;
}

__global__ void __launch_bounds__(BLOCK, 1)
spectral_rank2_kernel(const float4* __restrict__ in4, float4* __restrict__ out4) {
    __shared__ float sb1[2][NWARP];      // round 1: Sc, Ss partials
    __shared__ unsigned sq[2][NWARP];    // round 1: qmax, qmin partials (bits)
    __shared__ float sb2[3][NWARP];      // round 2: Gram partials
    const int t = threadIdx.x;
    const int lane = t & 31, w = t >> 5;

    // ---- Phase 1: load + feature transform.
    // sigmoid(|x|) = 1/(1+e), v ~= e, e = exp(-|x|).
    // Normalized feature direction: (1, q)/sqrt(1+q^2), q = e + e^2 > 0.
    float4 x4 = in4[t];
    float xs[4] = {x4.x, x4.y, x4.z, x4.w};
    float q[4], cw[4];
    float pc = 0.f, ps = 0.f;
    unsigned pqmx = 0u, pqmn = 0xffffffffu;
#pragma unroll
    for (int k = 0; k < 4; k++) {
        float e  = __expf(-fabsf(xs[k]));
        float qq = fmaf(e, e, e);                  // q = e + e^2
        float c  = rsqrtf(fmaf(qq, qq, 1.f));
        q[k] = qq; cw[k] = c;
        pc += c;
        ps = fmaf(qq, c, ps);
        unsigned qb = __float_as_uint(qq);
        pqmx = max(pqmx, qb);
        pqmn = min(pqmn, qb);
    }
    // ---- R1 level 1: warp partials (sums via shfl, extremes via HW REDUX).
    {
        float a = wsum_down(pc);
        float b = wsum_down(ps);
        unsigned m = redux_max_u32(pqmx);
        unsigned n = redux_min_u32(pqmn);
        if (lane == 0) { sb1[0][w] = a; sb1[1][w] = b; sq[0][w] = m; sq[1][w] = n; }
    }
    __syncthreads();
    // ---- R1 level 2: every warp reduces the 32 partials itself (butterfly /
    // REDUX) — result lands in all lanes, no broadcast or second barrier.
    const float Sc = wsum_bfly(sb1[0][lane]);
    const float Ss = wsum_bfly(sb1[1][lane]);
    const float qmx = __uint_as_float(redux_max_u32(sq[0][lane]));
    const float qmn = __uint_as_float(redux_min_u32(sq[1][lane]));

    // ---- Phase 2: dis = rsqrt(degree); cdis = c*dis; Gram partials.
    // u = cdis, v = q*cdis; A=sum u^2, B=sum uv, G=sum v^2.
    float cd[4];
    float pa = 0.f, pb = 0.f, pg = 0.f;
#pragma unroll
    for (int k = 0; k < 4; k++) {
        float d    = fmaf(q[k], Ss, Sc) * cw[k];   // degree
        float cdis = cw[k] * rsqrtf(d);
        cd[k] = cdis;
        float t2  = cdis * cdis;
        float t2q = t2 * q[k];
        pa += t2;
        pb += t2q;
        pg = fmaf(t2q, q[k], pg);
    }
    // ---- R2: same one-barrier two-level pattern.
    {
        float a = wsum_down(pa);
        float b = wsum_down(pb);
        float g = wsum_down(pg);
        if (lane == 0) { sb2[0][w] = a; sb2[1][w] = b; sb2[2][w] = g; }
    }
    __syncthreads();
    const float A = wsum_bfly(sb2[0][lane]);
    const float B = wsum_bfly(sb2[1][lane]);
    const float G = wsum_bfly(sb2[2][lane]);

    // ---- Phase 3 (per-thread, no barrier): 2x2 eigensolve, second eigenvalue.
    float diff = 0.5f * (A - G);
    float rr = sqrtf(fmaf(diff, diff, B * B));
    float al, be;
    if (diff >= 0.f) { al = B;         be = -(diff + rr); }
    else             { al = rr - diff; be = -B;            }

    // F is monotone in q -> extremes at q_min / q_max. Evaluate endpoints with
    // the EXACT same op sequence as the per-element path (bit-consistent).
    float Fe[2];
    float qe[2] = {qmn, qmx};
#pragma unroll
    for (int k = 0; k < 2; k++) {
        float c    = rsqrtf(fmaf(qe[k], qe[k], 1.f));
        float d    = fmaf(qe[k], Ss, Sc) * c;
        float cdis = c * rsqrtf(d);
        Fe[k] = fmaf(be, qe[k], al) * cdis;
    }
    float Fmn = fminf(Fe[0], Fe[1]);
    float Fmx = fmaxf(Fe[0], Fe[1]);
    float pivot = (fabsf(Fmx) >= fabsf(Fmn)) ? Fmx : Fmn;
    float sgn = (pivot >= 0.f) ? 1.f : -1.f;
    float mn = (sgn > 0.f) ? Fmn : -Fmx;
    float mx = (sgn > 0.f) ? Fmx : -Fmn;
    float scale = __fdividef(1.f, mx - mn + 1e-10f);
    float a1 = sgn * scale, a0 = -mn * scale;   // out = F*a1 + a0

    // ---- Phase 4: Fiedler values + fused normalize + store.
    float4 o;
    o.x = fmaf(fmaf(be, q[0], al) * cd[0], a1, a0);
    o.y = fmaf(fmaf(be, q[1], al) * cd[1], a1, a0);
    o.z = fmaf(fmaf(be, q[2], al) * cd[2], a1, a0);
    o.w = fmaf(fmaf(be, q[3], al) * cd[3], a1, a0);
    out4[t] = o;
}

extern "C" void kernel_launch(void* const* d_in, const int* in_sizes, int n_in,
                              void* d_out, int out_size) {
    (void)in_sizes; (void)n_in; (void)out_size;
    const float4* in = (const float4*)d_in[0];
    float4* out = (float4*)d_out;
    spectral_rank2_kernel<<<1, BLOCK>>>(in, out);
}